// round 3
// baseline (speedup 1.0000x reference)
#include <cuda_runtime.h>
#include <cuda_bf16.h>
#include <math.h>

// Problem constants
static constexpr int kB    = 8;
static constexpr int kS    = 4096;
static constexpr int kH    = 2048;
static constexpr int kHINT = 4;
static constexpr int kNB   = 513;   // 512 half-blocks + 1 zero block
static constexpr int kKDIM = 2052;  // H + HINT
static constexpr int kNW   = 512;   // number of windows
static constexpr int kMLP  = 64;

// Scratch: per-half-block masked sums (B, 513, 2052) + counts
__device__ float g_bsum[(size_t)kB * kNB * kKDIM];
__device__ float g_cnt[kB * kNB];

// ---------------------------------------------------------------------------
// Kernel 1: per-half-block masked sums.
//   bsum[b, blk, c] = sum_{k=0..7} mask(b, 8*blk+k) * feat(b, 8*blk+k, c)
//   where feat = [hidden (2048) | hint (4)], cnt = sum mask.
//   blk == 512 is a phantom all-zero block (window 511's upper half is OOB).
// Mask is uniform across the CTA per row -> skip the whole 8KB row load when 0.
// ---------------------------------------------------------------------------
__global__ __launch_bounds__(256) void k_pool(const float* __restrict__ hid,
                                              const int* __restrict__ am,
                                              const float* __restrict__ hint) {
    const int blk = blockIdx.x;   // 0..512
    const int b   = blockIdx.y;   // 0..7
    const int tid = threadIdx.x;  // 256 threads

    float* outp = g_bsum + ((size_t)b * kNB + blk) * kKDIM;

    if (blk == kNB - 1) {  // phantom zero block
        const float4 z = make_float4(0.f, 0.f, 0.f, 0.f);
        for (int i = tid; i < kKDIM / 4; i += 256)
            reinterpret_cast<float4*>(outp)[i] = z;
        if (tid == 0) g_cnt[b * kNB + blk] = 0.f;
        return;
    }

    __shared__ float sm[8];
    const int s0 = blk * 8;
    if (tid < 8) sm[tid] = (float)am[b * kS + s0 + tid];
    __syncthreads();

    float4 a0 = make_float4(0.f, 0.f, 0.f, 0.f);
    float4 a1 = a0;
    const float4* base = reinterpret_cast<const float4*>(hid + ((size_t)b * kS + s0) * kH);

#pragma unroll
    for (int k = 0; k < 8; k++) {
        const float w = sm[k];
        if (w != 0.f) {  // uniform across CTA -> real branch, skips 8KB load
            const float4* row = base + (size_t)k * (kH / 4);
            const float4 v0 = row[tid];
            const float4 v1 = row[tid + 256];
            a0.x += w * v0.x; a0.y += w * v0.y; a0.z += w * v0.z; a0.w += w * v0.w;
            a1.x += w * v1.x; a1.y += w * v1.y; a1.z += w * v1.z; a1.w += w * v1.w;
        }
    }
    reinterpret_cast<float4*>(outp)[tid]       = a0;
    reinterpret_cast<float4*>(outp)[tid + 256] = a1;

    if (tid < kHINT) {
        float acc = 0.f;
#pragma unroll
        for (int k = 0; k < 8; k++)
            acc += sm[k] * hint[((size_t)b * kS + s0 + k) * kHINT + tid];
        outp[kH + tid] = acc;
    }
    if (tid == 0) {
        float c = 0.f;
#pragma unroll
        for (int k = 0; k < 8; k++) c += sm[k];
        g_cnt[b * kNB + blk] = c;
    }
}

// ---------------------------------------------------------------------------
// Kernel 2: pooled = (bsum[w] + bsum[w+1]) / denom, then
//   logits = gelu(pooled @ W1 + b1) @ W2 + b2; also window_mask.
// Tiled GEMM: CTA = (batch b, 32 windows), N = 64 full, K tiled by 32 in smem.
// Thread t: mIdx = t&31 (window), jg = t>>5 (8 outputs j = 8*jg..8*jg+7).
// ---------------------------------------------------------------------------
__global__ __launch_bounds__(256) void k_mlp(const float* __restrict__ W1,
                                             const float* __restrict__ b1,
                                             const float* __restrict__ W2,
                                             const float* __restrict__ b2,
                                             float* __restrict__ out) {
    const int b   = blockIdx.y;
    const int w0  = blockIdx.x * 32;
    const int tid = threadIdx.x;
    const int mIdx = tid & 31;
    const int jg   = tid >> 5;
    const int j0   = jg * 8;

    __shared__ float s_pool[32][33];  // [kk][m], padded: conflict-free both ways
    __shared__ float s_w1[32][64];    // [kk][j]
    __shared__ float s_inv[32];
    __shared__ float s_red[8][32];

    if (tid < 32) {
        const int w = w0 + tid;
        const float c = g_cnt[b * kNB + w] + g_cnt[b * kNB + w + 1];
        s_inv[tid] = 1.f / fmaxf(c, 1.f);
        out[kB * kNW + b * kNW + w] = (c > 0.f) ? 1.f : 0.f;  // window_mask
    }
    __syncthreads();

    float acc[8];
#pragma unroll
    for (int i = 0; i < 8; i++) acc[i] = 0.f;

    const float* bs0 = g_bsum + ((size_t)b * kNB + w0) * kKDIM;
    const int pm = tid >> 3;        // window for pooled-tile load
    const int pk = (tid & 7) * 4;   // kk base (float4) for pooled-tile load

    for (int k0 = 0; k0 < kKDIM; k0 += 32) {
        // --- load W1 tile (32 x 64), coalesced float4 ---
#pragma unroll
        for (int i = 0; i < 2; i++) {
            const int idx = tid + i * 256;   // 0..511 float4 slots
            const int kk  = idx >> 4;
            const int c4  = idx & 15;
            const int k   = k0 + kk;
            float4 v = make_float4(0.f, 0.f, 0.f, 0.f);
            if (k < kKDIM)
                v = reinterpret_cast<const float4*>(W1)[(size_t)k * 16 + c4];
            *reinterpret_cast<float4*>(&s_w1[kk][c4 * 4]) = v;
        }
        // --- load pooled tile (32 windows x 32 k), combine halves + scale ---
        {
            const int k = k0 + pk;
            float4 v = make_float4(0.f, 0.f, 0.f, 0.f);
            if (k + 3 < kKDIM) {  // tail tile (k0=2048): only pk=0 is valid, exactly 4 elems
                const float* r0 = bs0 + (size_t)pm * kKDIM + k;
                const float4 u0 = *reinterpret_cast<const float4*>(r0);
                const float4 u1 = *reinterpret_cast<const float4*>(r0 + kKDIM);
                const float inv = s_inv[pm];
                v.x = (u0.x + u1.x) * inv;
                v.y = (u0.y + u1.y) * inv;
                v.z = (u0.z + u1.z) * inv;
                v.w = (u0.w + u1.w) * inv;
            }
            s_pool[pk + 0][pm] = v.x;
            s_pool[pk + 1][pm] = v.y;
            s_pool[pk + 2][pm] = v.z;
            s_pool[pk + 3][pm] = v.w;
        }
        __syncthreads();

#pragma unroll
        for (int kk = 0; kk < 32; kk++) {
            const float p = s_pool[kk][mIdx];
            const float4 wa = *reinterpret_cast<const float4*>(&s_w1[kk][j0]);
            const float4 wb = *reinterpret_cast<const float4*>(&s_w1[kk][j0 + 4]);
            acc[0] += p * wa.x; acc[1] += p * wa.y; acc[2] += p * wa.z; acc[3] += p * wa.w;
            acc[4] += p * wb.x; acc[5] += p * wb.y; acc[6] += p * wb.z; acc[7] += p * wb.w;
        }
        __syncthreads();
    }

    // epilogue: bias + exact gelu + dot with W2, reduce across 8 j-groups
    float partial = 0.f;
#pragma unroll
    for (int i = 0; i < 8; i++) {
        const float x = acc[i] + b1[j0 + i];
        const float g = 0.5f * x * (1.f + erff(x * 0.70710678118654752f));
        partial += g * W2[j0 + i];
    }
    s_red[jg][mIdx] = partial;
    __syncthreads();
    if (tid < 32) {
        float r = b2[0];
#pragma unroll
        for (int g = 0; g < 8; g++) r += s_red[g][tid];
        out[b * kNW + w0 + tid] = r;  // window_logits
    }
}

extern "C" void kernel_launch(void* const* d_in, const int* in_sizes, int n_in,
                              void* d_out, int out_size) {
    const float* hid  = (const float*)d_in[0];  // hidden_states (8,4096,2048)
    const int*   am   = (const int*)d_in[1];    // attention_mask (8,4096)
    const float* hint = (const float*)d_in[2];  // hint_features (8,4096,4)
    const float* W1   = (const float*)d_in[3];  // (2052,64)
    const float* b1   = (const float*)d_in[4];  // (64,)
    const float* W2   = (const float*)d_in[5];  // (64,1)
    const float* b2   = (const float*)d_in[6];  // (1,)
    float* out = (float*)d_out;                 // [logits (8*512) | mask (8*512)]

    dim3 g1(kNB, kB);
    k_pool<<<g1, 256>>>(hid, am, hint);
    dim3 g2(kNW / 32, kB);
    k_mlp<<<g2, 256>>>(W1, b1, W2, b2, out);
}

// round 4
// speedup vs baseline: 1.3786x; 1.3786x over previous
#include <cuda_runtime.h>
#include <cuda_bf16.h>
#include <math.h>

// Problem constants
static constexpr int kB    = 8;
static constexpr int kS    = 4096;
static constexpr int kH    = 2048;
static constexpr int kHINT = 4;
static constexpr int kNB   = 513;   // 512 half-blocks + 1 zero block
static constexpr int kKDIM = 2052;  // H + HINT
static constexpr int kNW   = 512;   // windows per batch
static constexpr int kM    = kB * kNW;  // 4096 GEMM rows
static constexpr int kSPLIT = 4;

// Scratch
__device__ float g_bsum[(size_t)kB * kNB * kKDIM];
__device__ float g_cnt[kB * kNB];
__device__ float g_part[(size_t)kSPLIT * kM * 64];   // split-K partials (pre-activation)

// ---------------------------------------------------------------------------
// Kernel 1: per-half-block masked sums (unchanged — near LTS cap already).
// ---------------------------------------------------------------------------
__global__ __launch_bounds__(256) void k_pool(const float* __restrict__ hid,
                                              const int* __restrict__ am,
                                              const float* __restrict__ hint) {
    const int blk = blockIdx.x;   // 0..512
    const int b   = blockIdx.y;   // 0..7
    const int tid = threadIdx.x;

    float* outp = g_bsum + ((size_t)b * kNB + blk) * kKDIM;

    if (blk == kNB - 1) {  // phantom zero block
        const float4 z = make_float4(0.f, 0.f, 0.f, 0.f);
        for (int i = tid; i < kKDIM / 4; i += 256)
            reinterpret_cast<float4*>(outp)[i] = z;
        if (tid == 0) g_cnt[b * kNB + blk] = 0.f;
        return;
    }

    __shared__ float sm[8];
    const int s0 = blk * 8;
    if (tid < 8) sm[tid] = (float)am[b * kS + s0 + tid];
    __syncthreads();

    float4 a0 = make_float4(0.f, 0.f, 0.f, 0.f);
    float4 a1 = a0;
    const float4* base = reinterpret_cast<const float4*>(hid + ((size_t)b * kS + s0) * kH);

#pragma unroll
    for (int k = 0; k < 8; k++) {
        const float w = sm[k];
        if (w != 0.f) {  // uniform across CTA -> skips 8KB row load
            const float4* row = base + (size_t)k * (kH / 4);
            const float4 v0 = row[tid];
            const float4 v1 = row[tid + 256];
            a0.x += w * v0.x; a0.y += w * v0.y; a0.z += w * v0.z; a0.w += w * v0.w;
            a1.x += w * v1.x; a1.y += w * v1.y; a1.z += w * v1.z; a1.w += w * v1.w;
        }
    }
    reinterpret_cast<float4*>(outp)[tid]       = a0;
    reinterpret_cast<float4*>(outp)[tid + 256] = a1;

    if (tid < kHINT) {
        float acc = 0.f;
#pragma unroll
        for (int k = 0; k < 8; k++)
            acc += sm[k] * hint[((size_t)b * kS + s0 + k) * kHINT + tid];
        outp[kH + tid] = acc;
    }
    if (tid == 0) {
        float c = 0.f;
#pragma unroll
        for (int k = 0; k < 8; k++) c += sm[k];
        g_cnt[b * kNB + blk] = c;
    }
}

// ---------------------------------------------------------------------------
// Kernel 2: split-K register-blocked GEMM with packed f32x2 FMA (FFMA2).
//   partial[kc][m][n] = sum_{k in chunk kc} pooled[m][k] * W1[k][n]
// CTA: 64 windows (one batch) x all 64 N, one K chunk. 128 threads.
// Per-thread tile 8m x 4n; A packed as adjacent-m f32x2 pairs straight from
// smem; B (W1) stored value-duplicated in smem so it loads pre-packed.
// ---------------------------------------------------------------------------
#define FMA2(d, a, bb) \
    asm("fma.rn.f32x2 %0, %1, %2, %3;" : "=l"(d) : "l"(a), "l"(bb), "l"(d))

__device__ __forceinline__ unsigned long long dup2(float x) {
    unsigned int u = __float_as_uint(x);
    return ((unsigned long long)u << 32) | (unsigned long long)u;
}
__device__ __forceinline__ float lo32(unsigned long long v) {
    return __uint_as_float((unsigned int)v);
}
__device__ __forceinline__ float hi32(unsigned long long v) {
    return __uint_as_float((unsigned int)(v >> 32));
}

__global__ __launch_bounds__(128) void k_mlp2(const float* __restrict__ W1,
                                              float* __restrict__ out) {
    const int wt  = blockIdx.x;   // window tile 0..7
    const int b   = blockIdx.y;   // batch 0..7
    const int kc  = blockIdx.z;   // K chunk 0..3
    const int w0  = wt * 64;
    const int tid = threadIdx.x;

    const int kBeg = kc * 512;
    const int kEnd = (kc == kSPLIT - 1) ? kKDIM : kBeg + 512;

    __shared__ float s_pool[32 * 72];               // [kk][w], stride 72 (16B-aligned rows)
    __shared__ unsigned long long s_w1d[32 * 64];   // [kk][n], value duplicated
    __shared__ float s_inv[64];

    if (tid < 64) {
        const int w = w0 + tid;
        const float c = g_cnt[b * kNB + w] + g_cnt[b * kNB + w + 1];
        s_inv[tid] = 1.f / fmaxf(c, 1.f);
        if (kc == 0)
            out[kB * kNW + b * kNW + w] = (c > 0.f) ? 1.f : 0.f;  // window_mask
    }
    __syncthreads();

    const int nt = tid & 15;       // n group
    const int mt = tid >> 4;       // m group
    const int n0 = nt * 4;
    const int m0 = mt * 8;

    // fill-stage thread mappings
    const int pw  = tid >> 1;           // pooled fill: window 0..63
    const int pkg = (tid & 1) * 16;     // pooled fill: kk base {0,16}
    const int fn4 = (tid & 15) * 4;     // w1 fill: n base
    const int fkb = (tid >> 4) * 4;     // w1 fill: kk base (x4 kk's)

    unsigned long long acc[4][4];
#pragma unroll
    for (int p = 0; p < 4; p++)
#pragma unroll
        for (int j = 0; j < 4; j++) acc[p][j] = 0ull;

    const float* bs = g_bsum + ((size_t)b * kNB + w0) * kKDIM;
    const float inv_pw = s_inv[pw];
    const float* r0 = bs + (size_t)pw * kKDIM;

    for (int t0 = kBeg; t0 < kEnd; t0 += 32) {
        // --- W1 tile, duplicated (32 kk x 64 n) ---
#pragma unroll
        for (int q = 0; q < 4; q++) {
            const int kk = fkb + q;
            const int k  = t0 + kk;
            float4 v = make_float4(0.f, 0.f, 0.f, 0.f);
            if (k < kKDIM)
                v = reinterpret_cast<const float4*>(W1)[(size_t)k * 16 + (fn4 >> 2)];
            unsigned long long* d = &s_w1d[kk * 64 + fn4];
            d[0] = dup2(v.x); d[1] = dup2(v.y); d[2] = dup2(v.z); d[3] = dup2(v.w);
        }
        // --- pooled tile (combine halves + scale), transposed to [kk][w] ---
#pragma unroll
        for (int j = 0; j < 4; j++) {
            const int kk = pkg + j * 4;
            const int k  = t0 + kk;
            float4 u0 = make_float4(0.f, 0.f, 0.f, 0.f), u1 = u0;
            if (k < kKDIM) {   // k is 4-aligned; row length 2052 is 4-aligned
                u0 = *reinterpret_cast<const float4*>(r0 + k);
                u1 = *reinterpret_cast<const float4*>(r0 + kKDIM + k);
            }
            s_pool[(kk + 0) * 72 + pw] = (u0.x + u1.x) * inv_pw;
            s_pool[(kk + 1) * 72 + pw] = (u0.y + u1.y) * inv_pw;
            s_pool[(kk + 2) * 72 + pw] = (u0.z + u1.z) * inv_pw;
            s_pool[(kk + 3) * 72 + pw] = (u0.w + u1.w) * inv_pw;
        }
        __syncthreads();

#pragma unroll
        for (int kk = 0; kk < 32; kk++) {
            const ulonglong2 A0 = *reinterpret_cast<const ulonglong2*>(&s_pool[kk * 72 + m0]);
            const ulonglong2 A1 = *reinterpret_cast<const ulonglong2*>(&s_pool[kk * 72 + m0 + 4]);
            const ulonglong2 B0 = *reinterpret_cast<const ulonglong2*>(&s_w1d[kk * 64 + n0]);
            const ulonglong2 B1 = *reinterpret_cast<const ulonglong2*>(&s_w1d[kk * 64 + n0 + 2]);
            FMA2(acc[0][0], A0.x, B0.x); FMA2(acc[0][1], A0.x, B0.y);
            FMA2(acc[0][2], A0.x, B1.x); FMA2(acc[0][3], A0.x, B1.y);
            FMA2(acc[1][0], A0.y, B0.x); FMA2(acc[1][1], A0.y, B0.y);
            FMA2(acc[1][2], A0.y, B1.x); FMA2(acc[1][3], A0.y, B1.y);
            FMA2(acc[2][0], A1.x, B0.x); FMA2(acc[2][1], A1.x, B0.y);
            FMA2(acc[2][2], A1.x, B1.x); FMA2(acc[2][3], A1.x, B1.y);
            FMA2(acc[3][0], A1.y, B0.x); FMA2(acc[3][1], A1.y, B0.y);
            FMA2(acc[3][2], A1.y, B1.x); FMA2(acc[3][3], A1.y, B1.y);
        }
        __syncthreads();
    }

    // write partials: rows m0..m0+7 (pair p -> m0+2p, m0+2p+1), cols n0..n0+3
    float* po = g_part + (((size_t)kc * kM) + (size_t)b * kNW + w0 + m0) * 64 + n0;
#pragma unroll
    for (int p = 0; p < 4; p++) {
        float4 lo, hi;
        lo.x = lo32(acc[p][0]); lo.y = lo32(acc[p][1]);
        lo.z = lo32(acc[p][2]); lo.w = lo32(acc[p][3]);
        hi.x = hi32(acc[p][0]); hi.y = hi32(acc[p][1]);
        hi.z = hi32(acc[p][2]); hi.w = hi32(acc[p][3]);
        *reinterpret_cast<float4*>(po + (size_t)(2 * p) * 64)     = lo;
        *reinterpret_cast<float4*>(po + (size_t)(2 * p + 1) * 64) = hi;
    }
}

// ---------------------------------------------------------------------------
// Kernel 3: reduce split-K partials + bias + exact gelu + dot W2 -> logits.
// One warp per GEMM row m; lane covers n = lane, lane+32.
// ---------------------------------------------------------------------------
__global__ __launch_bounds__(256) void k_fin(const float* __restrict__ b1,
                                             const float* __restrict__ W2,
                                             const float* __restrict__ b2,
                                             float* __restrict__ out) {
    const int m    = (blockIdx.x * 256 + threadIdx.x) >> 5;
    const int lane = threadIdx.x & 31;
    float r = 0.f;
#pragma unroll
    for (int h = 0; h < 2; h++) {
        const int n = lane + h * 32;
        float s = b1[n];
#pragma unroll
        for (int c = 0; c < kSPLIT; c++)
            s += g_part[((size_t)c * kM + m) * 64 + n];
        const float g = 0.5f * s * (1.f + erff(s * 0.70710678118654752f));
        r += g * W2[n];
    }
#pragma unroll
    for (int o = 16; o; o >>= 1) r += __shfl_xor_sync(0xffffffffu, r, o);
    if (lane == 0) out[m] = r + b2[0];   // out layout: m = b*512 + w
}

extern "C" void kernel_launch(void* const* d_in, const int* in_sizes, int n_in,
                              void* d_out, int out_size) {
    const float* hid  = (const float*)d_in[0];  // hidden_states (8,4096,2048)
    const int*   am   = (const int*)d_in[1];    // attention_mask (8,4096)
    const float* hint = (const float*)d_in[2];  // hint_features (8,4096,4)
    const float* W1   = (const float*)d_in[3];  // (2052,64)
    const float* b1   = (const float*)d_in[4];  // (64,)
    const float* W2   = (const float*)d_in[5];  // (64,1)
    const float* b2   = (const float*)d_in[6];  // (1,)
    float* out = (float*)d_out;                 // [logits (8*512) | mask (8*512)]

    dim3 g1(kNB, kB);
    k_pool<<<g1, 256>>>(hid, am, hint);

    dim3 g2(kNW / 64, kB, kSPLIT);              // 8 x 8 x 4 = 256 CTAs
    k_mlp2<<<g2, 128>>>(W1, out);

    k_fin<<<kM * 32 / 256, 256>>>(b1, W2, b2, out);
}

// round 8
// speedup vs baseline: 1.4691x; 1.0657x over previous
#include <cuda_runtime.h>
#include <cuda_bf16.h>
#include <math.h>

// Problem constants
static constexpr int kB    = 8;
static constexpr int kS    = 4096;
static constexpr int kH    = 2048;
static constexpr int kHINT = 4;
static constexpr int kNB   = 513;   // 512 half-blocks + 1 zero block
static constexpr int kKDIM = 2052;  // H + HINT
static constexpr int kNW   = 512;   // windows per batch
static constexpr int kM    = kB * kNW;  // 4096 GEMM rows
static constexpr int kSPLIT = 8;
static constexpr int kCHUNK = 256;      // last chunk = 2052 - 7*256 = 260

// Scratch
__device__ float g_bsum[(size_t)kB * kNB * kKDIM];
__device__ float g_cnt[kB * kNB];
__device__ float g_part[(size_t)kSPLIT * kM * 64];   // split-K partials (pre-activation)

// ---------------------------------------------------------------------------
// Kernel 1: per-half-block masked sums (unchanged — at memory ceiling).
// ---------------------------------------------------------------------------
__global__ __launch_bounds__(256) void k_pool(const float* __restrict__ hid,
                                              const int* __restrict__ am,
                                              const float* __restrict__ hint) {
    const int blk = blockIdx.x;   // 0..512
    const int b   = blockIdx.y;   // 0..7
    const int tid = threadIdx.x;

    float* outp = g_bsum + ((size_t)b * kNB + blk) * kKDIM;

    if (blk == kNB - 1) {  // phantom zero block
        const float4 z = make_float4(0.f, 0.f, 0.f, 0.f);
        for (int i = tid; i < kKDIM / 4; i += 256)
            reinterpret_cast<float4*>(outp)[i] = z;
        if (tid == 0) g_cnt[b * kNB + blk] = 0.f;
        return;
    }

    __shared__ float sm[8];
    const int s0 = blk * 8;
    if (tid < 8) sm[tid] = (float)am[b * kS + s0 + tid];
    __syncthreads();

    float4 a0 = make_float4(0.f, 0.f, 0.f, 0.f);
    float4 a1 = a0;
    const float4* base = reinterpret_cast<const float4*>(hid + ((size_t)b * kS + s0) * kH);

#pragma unroll
    for (int k = 0; k < 8; k++) {
        const float w = sm[k];
        if (w != 0.f) {  // uniform across CTA -> skips 8KB row load
            const float4* row = base + (size_t)k * (kH / 4);
            const float4 v0 = row[tid];
            const float4 v1 = row[tid + 256];
            a0.x += w * v0.x; a0.y += w * v0.y; a0.z += w * v0.z; a0.w += w * v0.w;
            a1.x += w * v1.x; a1.y += w * v1.y; a1.z += w * v1.z; a1.w += w * v1.w;
        }
    }
    reinterpret_cast<float4*>(outp)[tid]       = a0;
    reinterpret_cast<float4*>(outp)[tid + 256] = a1;

    if (tid < kHINT) {
        float acc = 0.f;
#pragma unroll
        for (int k = 0; k < 8; k++)
            acc += sm[k] * hint[((size_t)b * kS + s0 + k) * kHINT + tid];
        outp[kH + tid] = acc;
    }
    if (tid == 0) {
        float c = 0.f;
#pragma unroll
        for (int k = 0; k < 8; k++) c += sm[k];
        g_cnt[b * kNB + blk] = c;
    }
}

// ---------------------------------------------------------------------------
// Kernel 2: split-K register-blocked GEMM, packed f32x2 FMA, double-buffered
// smem with register staging (1 syncthreads per k-tile, global loads for the
// next tile overlap compute of the current one).
// CTA: 64 windows x 64 N x one K chunk, 128 threads, per-thread 8m x 4n.
// ---------------------------------------------------------------------------
#define FMA2(d, a, bb) \
    asm("fma.rn.f32x2 %0, %1, %2, %3;" : "=l"(d) : "l"(a), "l"(bb), "l"(d))

__device__ __forceinline__ unsigned long long dup2(float x) {
    unsigned int u = __float_as_uint(x);
    return ((unsigned long long)u << 32) | (unsigned long long)u;
}
__device__ __forceinline__ float lo32(unsigned long long v) {
    return __uint_as_float((unsigned int)v);
}
__device__ __forceinline__ float hi32(unsigned long long v) {
    return __uint_as_float((unsigned int)(v >> 32));
}

__global__ __launch_bounds__(128) void k_mlp2(const float* __restrict__ W1,
                                              float* __restrict__ out) {
    const int wt  = blockIdx.x;   // window tile 0..7
    const int b   = blockIdx.y;   // batch 0..7
    const int kc  = blockIdx.z;   // K chunk 0..7
    const int w0  = wt * 64;
    const int tid = threadIdx.x;

    const int kBeg = kc * kCHUNK;
    const int kEnd = (kc == kSPLIT - 1) ? kKDIM : kBeg + kCHUNK;

    __shared__ float s_pool[2][32 * 72];               // [buf][kk][w]
    __shared__ unsigned long long s_w1d[2][32 * 64];   // [buf][kk][n] duplicated
    __shared__ float s_inv[64];

    if (tid < 64) {
        const int w = w0 + tid;
        const float c = g_cnt[b * kNB + w] + g_cnt[b * kNB + w + 1];
        s_inv[tid] = 1.f / fmaxf(c, 1.f);
        if (kc == 0)
            out[kB * kNW + b * kNW + w] = (c > 0.f) ? 1.f : 0.f;  // window_mask
    }
    __syncthreads();

    const int nt = tid & 15;       // n group
    const int mt = tid >> 4;       // m group
    const int n0 = nt * 4;
    const int m0 = mt * 8;

    // fill-stage thread mappings
    const int pw  = tid >> 1;           // pooled fill: window 0..63
    const int pkg = (tid & 1) * 16;     // pooled fill: kk base {0,16}
    const int fn4 = (tid & 15) * 4;     // w1 fill: n base
    const int fkb = (tid >> 4) * 4;     // w1 fill: kk base (4 consecutive kk)

    unsigned long long acc[4][4];
#pragma unroll
    for (int p = 0; p < 4; p++)
#pragma unroll
        for (int j = 0; j < 4; j++) acc[p][j] = 0ull;

    const float* bs = g_bsum + ((size_t)b * kNB + w0) * kKDIM;
    const float inv_pw = s_inv[pw];
    const float* r0 = bs + (size_t)pw * kKDIM;

    // register staging buffers
    float4 rw[4];            // W1 rows
    float4 ru0[4], ru1[4];   // pooled rows w, w+1

    // stage(t0): global -> regs
    auto stage = [&](int t0) {
#pragma unroll
        for (int q = 0; q < 4; q++) {
            const int k = t0 + fkb + q;
            rw[q] = make_float4(0.f, 0.f, 0.f, 0.f);
            if (k < kKDIM)
                rw[q] = reinterpret_cast<const float4*>(W1)[(size_t)k * 16 + (fn4 >> 2)];
        }
#pragma unroll
        for (int j = 0; j < 4; j++) {
            const int k = t0 + pkg + j * 4;
            ru0[j] = make_float4(0.f, 0.f, 0.f, 0.f);
            ru1[j] = ru0[j];
            if (k < kKDIM) {
                ru0[j] = *reinterpret_cast<const float4*>(r0 + k);
                ru1[j] = *reinterpret_cast<const float4*>(r0 + kKDIM + k);
            }
        }
    };

    // commit(buf): regs -> smem
    auto commit = [&](int buf) {
#pragma unroll
        for (int q = 0; q < 4; q++) {
            const int kk = fkb + q;
            unsigned long long* d = &s_w1d[buf][kk * 64 + fn4];
            d[0] = dup2(rw[q].x); d[1] = dup2(rw[q].y);
            d[2] = dup2(rw[q].z); d[3] = dup2(rw[q].w);
        }
#pragma unroll
        for (int j = 0; j < 4; j++) {
            const int kk = pkg + j * 4;
            s_pool[buf][(kk + 0) * 72 + pw] = (ru0[j].x + ru1[j].x) * inv_pw;
            s_pool[buf][(kk + 1) * 72 + pw] = (ru0[j].y + ru1[j].y) * inv_pw;
            s_pool[buf][(kk + 2) * 72 + pw] = (ru0[j].z + ru1[j].z) * inv_pw;
            s_pool[buf][(kk + 3) * 72 + pw] = (ru0[j].w + ru1[j].w) * inv_pw;
        }
    };

    stage(kBeg);
    int buf = 0;
    for (int t0 = kBeg; t0 < kEnd; t0 += 32, buf ^= 1) {
        commit(buf);
        __syncthreads();
        if (t0 + 32 < kEnd) stage(t0 + 32);   // overlap next-tile LDG with compute

        const float* sp = &s_pool[buf][0];
        const unsigned long long* sw = &s_w1d[buf][0];
#pragma unroll
        for (int kk = 0; kk < 32; kk++) {
            const ulonglong2 A0 = *reinterpret_cast<const ulonglong2*>(sp + kk * 72 + m0);
            const ulonglong2 A1 = *reinterpret_cast<const ulonglong2*>(sp + kk * 72 + m0 + 4);
            const ulonglong2 B0 = *reinterpret_cast<const ulonglong2*>(sw + kk * 64 + n0);
            const ulonglong2 B1 = *reinterpret_cast<const ulonglong2*>(sw + kk * 64 + n0 + 2);
            FMA2(acc[0][0], A0.x, B0.x); FMA2(acc[0][1], A0.x, B0.y);
            FMA2(acc[0][2], A0.x, B1.x); FMA2(acc[0][3], A0.x, B1.y);
            FMA2(acc[1][0], A0.y, B0.x); FMA2(acc[1][1], A0.y, B0.y);
            FMA2(acc[1][2], A0.y, B1.x); FMA2(acc[1][3], A0.y, B1.y);
            FMA2(acc[2][0], A1.x, B0.x); FMA2(acc[2][1], A1.x, B0.y);
            FMA2(acc[2][2], A1.x, B1.x); FMA2(acc[2][3], A1.x, B1.y);
            FMA2(acc[3][0], A1.y, B0.x); FMA2(acc[3][1], A1.y, B0.y);
            FMA2(acc[3][2], A1.y, B1.x); FMA2(acc[3][3], A1.y, B1.y);
        }
        // no second sync needed: next iteration's commit writes the OTHER
        // buffer; the single barrier orders that commit against these reads.
    }

    // write partials: rows m0..m0+7 (pair p -> m0+2p, m0+2p+1), cols n0..n0+3
    float* po = g_part + (((size_t)kc * kM) + (size_t)b * kNW + w0 + m0) * 64 + n0;
#pragma unroll
    for (int p = 0; p < 4; p++) {
        float4 lo, hi;
        lo.x = lo32(acc[p][0]); lo.y = lo32(acc[p][1]);
        lo.z = lo32(acc[p][2]); lo.w = lo32(acc[p][3]);
        hi.x = hi32(acc[p][0]); hi.y = hi32(acc[p][1]);
        hi.z = hi32(acc[p][2]); hi.w = hi32(acc[p][3]);
        *reinterpret_cast<float4*>(po + (size_t)(2 * p) * 64)     = lo;
        *reinterpret_cast<float4*>(po + (size_t)(2 * p + 1) * 64) = hi;
    }
}

// ---------------------------------------------------------------------------
// Kernel 3: reduce split-K partials + bias + exact gelu + dot W2 -> logits.
// One warp per GEMM row m; lane covers n = lane, lane+32.
// ---------------------------------------------------------------------------
__global__ __launch_bounds__(256) void k_fin(const float* __restrict__ b1,
                                             const float* __restrict__ W2,
                                             const float* __restrict__ b2,
                                             float* __restrict__ out) {
    const int m    = (blockIdx.x * 256 + threadIdx.x) >> 5;
    const int lane = threadIdx.x & 31;
    float r = 0.f;
#pragma unroll
    for (int h = 0; h < 2; h++) {
        const int n = lane + h * 32;
        float s = b1[n];
#pragma unroll
        for (int c = 0; c < kSPLIT; c++)
            s += g_part[((size_t)c * kM + m) * 64 + n];
        const float g = 0.5f * s * (1.f + erff(s * 0.70710678118654752f));
        r += g * W2[n];
    }
#pragma unroll
    for (int o = 16; o; o >>= 1) r += __shfl_xor_sync(0xffffffffu, r, o);
    if (lane == 0) out[m] = r + b2[0];   // out layout: m = b*512 + w
}

extern "C" void kernel_launch(void* const* d_in, const int* in_sizes, int n_in,
                              void* d_out, int out_size) {
    const float* hid  = (const float*)d_in[0];  // hidden_states (8,4096,2048)
    const int*   am   = (const int*)d_in[1];    // attention_mask (8,4096)
    const float* hint = (const float*)d_in[2];  // hint_features (8,4096,4)
    const float* W1   = (const float*)d_in[3];  // (2052,64)
    const float* b1   = (const float*)d_in[4];  // (64,)
    const float* W2   = (const float*)d_in[5];  // (64,1)
    const float* b2   = (const float*)d_in[6];  // (1,)
    float* out = (float*)d_out;                 // [logits (8*512) | mask (8*512)]

    dim3 g1(kNB, kB);
    k_pool<<<g1, 256>>>(hid, am, hint);

    dim3 g2(kNW / 64, kB, kSPLIT);              // 8 x 8 x 8 = 512 CTAs
    k_mlp2<<<g2, 128>>>(W1, out);

    k_fin<<<kM * 32 / 256, 256>>>(b1, W2, b2, out);
}

// round 9
// speedup vs baseline: 1.8370x; 1.2504x over previous
#include <cuda_runtime.h>
#include <cuda_bf16.h>
#include <math.h>

// Problem constants
static constexpr int kB    = 8;
static constexpr int kS    = 4096;
static constexpr int kH    = 2048;
static constexpr int kHINT = 4;
static constexpr int kNB   = 513;   // 512 half-blocks + 1 zero block per batch
static constexpr int kKDIM = 2052;  // H + HINT
static constexpr int kNW   = 512;   // windows per batch
static constexpr int kMR   = kB * kNB;   // 4104 real GEMM rows (half-blocks)
static constexpr int kMT   = 64;         // GEMM m-tile
static constexpr int kMP   = 4160;       // padded rows = 65 * 64
static constexpr int kSPLIT = 8;
static constexpr int kCHUNK = 256;       // last chunk = 2052 - 7*256 = 260

// smem row strides (conflict-free + 16B-aligned ull2 access)
static constexpr int kAS = 66;   // s_a row stride in ulonglong (even -> ull2 aligned)
static constexpr int kBS = 68;   // s_b row stride in floats (272B, != 0 mod 128)

// Scratch
__device__ float g_bsum[(size_t)kMP * kKDIM];        // rows >= 4104 are never read meaningfully
__device__ float g_cnt[kMR];
__device__ float g_part[(size_t)kSPLIT * kMP * 64];  // split-K partials of bsum @ W1

// ---------------------------------------------------------------------------
// Kernel 1: per-half-block masked sums (unchanged — at memory ceiling).
// ---------------------------------------------------------------------------
__global__ __launch_bounds__(256) void k_pool(const float* __restrict__ hid,
                                              const int* __restrict__ am,
                                              const float* __restrict__ hint) {
    const int blk = blockIdx.x;   // 0..512
    const int b   = blockIdx.y;   // 0..7
    const int tid = threadIdx.x;

    float* outp = g_bsum + ((size_t)(b * kNB + blk)) * kKDIM;

    if (blk == kNB - 1) {  // phantom zero block
        const float4 z = make_float4(0.f, 0.f, 0.f, 0.f);
        for (int i = tid; i < kKDIM / 4; i += 256)
            reinterpret_cast<float4*>(outp)[i] = z;
        if (tid == 0) g_cnt[b * kNB + blk] = 0.f;
        return;
    }

    __shared__ float sm[8];
    const int s0 = blk * 8;
    if (tid < 8) sm[tid] = (float)am[b * kS + s0 + tid];
    __syncthreads();

    float4 a0 = make_float4(0.f, 0.f, 0.f, 0.f);
    float4 a1 = a0;
    const float4* base = reinterpret_cast<const float4*>(hid + ((size_t)b * kS + s0) * kH);

#pragma unroll
    for (int k = 0; k < 8; k++) {
        const float w = sm[k];
        if (w != 0.f) {  // uniform across CTA -> skips 8KB row load
            const float4* row = base + (size_t)k * (kH / 4);
            const float4 v0 = row[tid];
            const float4 v1 = row[tid + 256];
            a0.x += w * v0.x; a0.y += w * v0.y; a0.z += w * v0.z; a0.w += w * v0.w;
            a1.x += w * v1.x; a1.y += w * v1.y; a1.z += w * v1.z; a1.w += w * v1.w;
        }
    }
    reinterpret_cast<float4*>(outp)[tid]       = a0;
    reinterpret_cast<float4*>(outp)[tid + 256] = a1;

    if (tid < kHINT) {
        float acc = 0.f;
#pragma unroll
        for (int k = 0; k < 8; k++)
            acc += sm[k] * hint[((size_t)b * kS + s0 + k) * kHINT + tid];
        outp[kH + tid] = acc;
    }
    if (tid == 0) {
        float c = 0.f;
#pragma unroll
        for (int k = 0; k < 8; k++) c += sm[k];
        g_cnt[b * kNB + blk] = c;
    }
}

// ---------------------------------------------------------------------------
// Kernel 2: plain split-K GEMM  part = g_bsum[4160 x 2052] @ W1[2052 x 64].
// n-packed f32x2: acc holds n-pairs; B loads are naturally packed plain floats
// (no duplication, conflict-free), A is stored duplicated in smem (reads are
// warp-broadcast, ~free on the crossbar).
// CTA: 64 m x 64 n x one K chunk, 128 threads, per-thread 8m x 4n.
// ---------------------------------------------------------------------------
#define FMA2(d, a, bb) \
    asm("fma.rn.f32x2 %0, %1, %2, %3;" : "=l"(d) : "l"(a), "l"(bb), "l"(d))

__device__ __forceinline__ unsigned long long dup2(float x) {
    unsigned int u = __float_as_uint(x);
    return ((unsigned long long)u << 32) | (unsigned long long)u;
}
__device__ __forceinline__ float lo32(unsigned long long v) {
    return __uint_as_float((unsigned int)v);
}
__device__ __forceinline__ float hi32(unsigned long long v) {
    return __uint_as_float((unsigned int)(v >> 32));
}

__global__ __launch_bounds__(128) void k_gemm(const float* __restrict__ W1) {
    const int mt0 = blockIdx.x * kMT;   // 0, 64, ..., 4096 (65 tiles)
    const int kc  = blockIdx.y;         // 0..7
    const int tid = threadIdx.x;

    const int kBeg = kc * kCHUNK;
    const int kEnd = (kc == kSPLIT - 1) ? kKDIM : kBeg + kCHUNK;

    __shared__ __align__(16) unsigned long long s_a[2][32 * kAS];  // [buf][kk][m] dup'd
    __shared__ __align__(16) float s_b[2][32 * kBS];               // [buf][kk][n] plain

    const int nt = tid & 15;       // n group
    const int mt = tid >> 4;       // m group
    const int n0 = nt * 4;         // 4 n = 2 n-pairs
    const int m0 = mt * 8;         // 8 m rows

    // fill mappings
    const int pw  = tid & 63;           // A fill: row-in-tile 0..63 (whole warp same k-half)
    const int pk0 = (tid >> 6) * 16;    // A fill: kk base {0,16}

    unsigned long long acc[8][2];
#pragma unroll
    for (int p = 0; p < 8; p++) { acc[p][0] = 0ull; acc[p][1] = 0ull; }

    const float* ar = g_bsum + (size_t)(mt0 + pw) * kKDIM;  // this thread's A source row

    float4 ra[4];   // A staging: 16 k values of row pw
    float4 rb[4];   // B staging: 4 float4 of W1 tile

    auto stage = [&](int t0) {
#pragma unroll
        for (int q = 0; q < 4; q++) {
            const int k = t0 + pk0 + q * 4;
            ra[q] = make_float4(0.f, 0.f, 0.f, 0.f);
            if (k < kEnd)  // kEnd and k are 4-aligned
                ra[q] = *reinterpret_cast<const float4*>(ar + k);
        }
#pragma unroll
        for (int i = 0; i < 4; i++) {
            const int slot = tid + 128 * i;     // 0..511
            const int kk = slot >> 4;
            const int c4 = slot & 15;
            const int k  = t0 + kk;
            rb[i] = make_float4(0.f, 0.f, 0.f, 0.f);
            if (k < kEnd)
                rb[i] = reinterpret_cast<const float4*>(W1)[(size_t)k * 16 + c4];
        }
    };

    auto commit = [&](int buf) {
#pragma unroll
        for (int q = 0; q < 4; q++) {
            const int kk = pk0 + q * 4;
            unsigned long long* d = &s_a[buf][kk * kAS + pw];
            d[0 * kAS] = dup2(ra[q].x);
            d[1 * kAS] = dup2(ra[q].y);
            d[2 * kAS] = dup2(ra[q].z);
            d[3 * kAS] = dup2(ra[q].w);
        }
#pragma unroll
        for (int i = 0; i < 4; i++) {
            const int slot = tid + 128 * i;
            const int kk = slot >> 4;
            const int c4 = slot & 15;
            *reinterpret_cast<float4*>(&s_b[buf][kk * kBS + c4 * 4]) = rb[i];
        }
    };

    stage(kBeg);
    int buf = 0;
    for (int t0 = kBeg; t0 < kEnd; t0 += 32, buf ^= 1) {
        commit(buf);
        __syncthreads();
        if (t0 + 32 < kEnd) stage(t0 + 32);   // overlap next-tile LDG with compute

        const unsigned long long* sa = &s_a[buf][0];
        const float* sb = &s_b[buf][0];
#pragma unroll
        for (int kk = 0; kk < 32; kk++) {
            const unsigned long long* ap = sa + kk * kAS + m0;
            const ulonglong2 A01 = *reinterpret_cast<const ulonglong2*>(ap);
            const ulonglong2 A23 = *reinterpret_cast<const ulonglong2*>(ap + 2);
            const ulonglong2 A45 = *reinterpret_cast<const ulonglong2*>(ap + 4);
            const ulonglong2 A67 = *reinterpret_cast<const ulonglong2*>(ap + 6);
            const ulonglong2 Bv  = *reinterpret_cast<const ulonglong2*>(sb + kk * kBS + n0);
            FMA2(acc[0][0], A01.x, Bv.x); FMA2(acc[0][1], A01.x, Bv.y);
            FMA2(acc[1][0], A01.y, Bv.x); FMA2(acc[1][1], A01.y, Bv.y);
            FMA2(acc[2][0], A23.x, Bv.x); FMA2(acc[2][1], A23.x, Bv.y);
            FMA2(acc[3][0], A23.y, Bv.x); FMA2(acc[3][1], A23.y, Bv.y);
            FMA2(acc[4][0], A45.x, Bv.x); FMA2(acc[4][1], A45.x, Bv.y);
            FMA2(acc[5][0], A45.y, Bv.x); FMA2(acc[5][1], A45.y, Bv.y);
            FMA2(acc[6][0], A67.x, Bv.x); FMA2(acc[6][1], A67.x, Bv.y);
            FMA2(acc[7][0], A67.y, Bv.x); FMA2(acc[7][1], A67.y, Bv.y);
        }
        // single barrier per tile: next commit writes the OTHER buffer.
    }

    // write partials: rows mt0+m0..+7, cols n0..n0+3
    float* po = g_part + ((size_t)kc * kMP + mt0 + m0) * 64 + n0;
#pragma unroll
    for (int p = 0; p < 8; p++) {
        float4 v;
        v.x = lo32(acc[p][0]); v.y = hi32(acc[p][0]);
        v.z = lo32(acc[p][1]); v.w = hi32(acc[p][1]);
        *reinterpret_cast<float4*>(po + (size_t)p * 64) = v;
    }
}

// ---------------------------------------------------------------------------
// Kernel 3: per window w: y = (part rows r0 + r0+1 summed over chunks) * inv,
// then bias + exact gelu + dot W2 -> logits; also window_mask.
// One warp per window; lane covers n = lane, lane+32.
// ---------------------------------------------------------------------------
__global__ __launch_bounds__(256) void k_fin(const float* __restrict__ b1,
                                             const float* __restrict__ W2,
                                             const float* __restrict__ b2,
                                             float* __restrict__ out) {
    const int w    = (blockIdx.x * 256 + threadIdx.x) >> 5;  // 0..4095 = b*512 + wi
    const int lane = threadIdx.x & 31;
    const int b    = w >> 9;
    const int wi   = w & 511;
    const int r0   = b * kNB + wi;          // half-block rows r0, r0+1

    const float cnt = g_cnt[r0] + g_cnt[r0 + 1];
    const float inv = 1.f / fmaxf(cnt, 1.f);
    if (lane == 0) out[kB * kNW + w] = (cnt > 0.f) ? 1.f : 0.f;  // window_mask

    float r = 0.f;
#pragma unroll
    for (int h = 0; h < 2; h++) {
        const int n = lane + h * 32;
        float s = 0.f;
#pragma unroll
        for (int c = 0; c < kSPLIT; c++) {
            const float* pc = g_part + ((size_t)c * kMP + r0) * 64 + n;
            s += pc[0] + pc[64];
        }
        const float x = s * inv + b1[n];
        const float g = 0.5f * x * (1.f + erff(x * 0.70710678118654752f));
        r += g * W2[n];
    }
#pragma unroll
    for (int o = 16; o; o >>= 1) r += __shfl_xor_sync(0xffffffffu, r, o);
    if (lane == 0) out[w] = r + b2[0];   // window_logits
}

extern "C" void kernel_launch(void* const* d_in, const int* in_sizes, int n_in,
                              void* d_out, int out_size) {
    const float* hid  = (const float*)d_in[0];  // hidden_states (8,4096,2048)
    const int*   am   = (const int*)d_in[1];    // attention_mask (8,4096)
    const float* hint = (const float*)d_in[2];  // hint_features (8,4096,4)
    const float* W1   = (const float*)d_in[3];  // (2052,64)
    const float* b1   = (const float*)d_in[4];  // (64,)
    const float* W2   = (const float*)d_in[5];  // (64,1)
    const float* b2   = (const float*)d_in[6];  // (1,)
    float* out = (float*)d_out;                 // [logits (8*512) | mask (8*512)]

    dim3 g1(kNB, kB);
    k_pool<<<g1, 256>>>(hid, am, hint);

    dim3 g2(kMP / kMT, kSPLIT);                 // 65 x 8 = 520 CTAs, one wave @ 4/SM
    k_gemm<<<g2, 128>>>(W1);

    k_fin<<<kB * kNW * 32 / 256, 256>>>(b1, W2, b2, out);
}

// round 12
// speedup vs baseline: 2.4348x; 1.3254x over previous
#include <cuda_runtime.h>
#include <cuda_bf16.h>
#include <math.h>
#include <stdint.h>

// Problem constants
static constexpr int kB    = 8;
static constexpr int kS    = 4096;
static constexpr int kH    = 2048;
static constexpr int kHINT = 4;
static constexpr int kNBpB = 512;        // half-blocks per batch
static constexpr int kKDIM = 2052;       // H + HINT
static constexpr int kNW   = 512;        // windows per batch
static constexpr int kMR   = kB * kNBpB; // 4096 GEMM rows = 32 m-tiles of 128
static constexpr int kSPLIT = 4;

// Scratch
__device__ float g_bsum[(size_t)kMR * kKDIM];
__device__ float g_cnt[kMR];
__device__ float g_part[(size_t)kSPLIT * kMR * 64];

// ---------------------------------------------------------------------------
// Kernel 1: per-half-block masked sums (unchanged — at memory ceiling).
// ---------------------------------------------------------------------------
__global__ __launch_bounds__(256) void k_pool(const float* __restrict__ hid,
                                              const int* __restrict__ am,
                                              const float* __restrict__ hint) {
    const int blk = blockIdx.x;   // 0..511
    const int b   = blockIdx.y;   // 0..7
    const int tid = threadIdx.x;

    float* outp = g_bsum + (size_t)(b * kNBpB + blk) * kKDIM;

    __shared__ float sm[8];
    const int s0 = blk * 8;
    if (tid < 8) sm[tid] = (float)am[b * kS + s0 + tid];
    __syncthreads();

    float4 a0 = make_float4(0.f, 0.f, 0.f, 0.f);
    float4 a1 = a0;
    const float4* base = reinterpret_cast<const float4*>(hid + ((size_t)b * kS + s0) * kH);

#pragma unroll
    for (int k = 0; k < 8; k++) {
        const float w = sm[k];
        if (w != 0.f) {  // uniform across CTA -> skips 8KB row load
            const float4* row = base + (size_t)k * (kH / 4);
            const float4 v0 = row[tid];
            const float4 v1 = row[tid + 256];
            a0.x += w * v0.x; a0.y += w * v0.y; a0.z += w * v0.z; a0.w += w * v0.w;
            a1.x += w * v1.x; a1.y += w * v1.y; a1.z += w * v1.z; a1.w += w * v1.w;
        }
    }
    reinterpret_cast<float4*>(outp)[tid]       = a0;
    reinterpret_cast<float4*>(outp)[tid + 256] = a1;

    if (tid < kHINT) {
        float acc = 0.f;
#pragma unroll
        for (int k = 0; k < 8; k++)
            acc += sm[k] * hint[((size_t)b * kS + s0 + k) * kHINT + tid];
        outp[kH + tid] = acc;
    }
    if (tid == 0) {
        float c = 0.f;
#pragma unroll
        for (int k = 0; k < 8; k++) c += sm[k];
        g_cnt[b * kNBpB + blk] = c;
    }
}

// ---------------------------------------------------------------------------
// mma.sync m16n8k16 bf16 (sm_80+ base-target instruction; HMMA on sm_103)
// ---------------------------------------------------------------------------
__device__ __forceinline__ void mma16816(float& d0, float& d1, float& d2, float& d3,
                                         uint32_t a0, uint32_t a1, uint32_t a2, uint32_t a3,
                                         uint32_t b0, uint32_t b1) {
    asm volatile(
        "mma.sync.aligned.m16n8k16.row.col.f32.bf16.bf16.f32 "
        "{%0,%1,%2,%3}, {%4,%5,%6,%7}, {%8,%9}, {%0,%1,%2,%3};"
        : "+f"(d0), "+f"(d1), "+f"(d2), "+f"(d3)
        : "r"(a0), "r"(a1), "r"(a2), "r"(a3), "r"(b0), "r"(b1));
}

__device__ __forceinline__ uint32_t pack_hi(float x, float y, uint32_t& lo) {
    __nv_bfloat162 h = __float22bfloat162_rn(make_float2(x, y));
    float rx = x - __bfloat162float(__low2bfloat16(h));
    float ry = y - __bfloat162float(__high2bfloat16(h));
    __nv_bfloat162 l = __float22bfloat162_rn(make_float2(rx, ry));
    lo = *reinterpret_cast<uint32_t*>(&l);
    return *reinterpret_cast<uint32_t*>(&h);
}

// smem layout (u32 units), row stride 20 u32 (80B) -> conflict-free frag loads
static constexpr int kRS   = 20;
static constexpr int kAh   = 0;            // 128 rows
static constexpr int kAl   = 128 * kRS;    // 2560
static constexpr int kBh   = 256 * kRS;    // 5120
static constexpr int kBl   = 320 * kRS;    // 6400
static constexpr int kBufU = 384 * kRS;    // 7680 u32 = 30720 B per buffer
static constexpr int kSmemDyn = 2 * kBufU * 4;   // 61440 B

// ---------------------------------------------------------------------------
// Kernel 2: split-precision bf16 tensor GEMM  g_part[kc] = bsum[:,kslice] @ W1.
// CTA: 128m x 64n, one K chunk (512/516); 8 warps (4m x 2n), warp 32m x 32n.
// 3 terms: AhBh + AlBh + AhBl, fp32 accumulate. Double-buffered, 1 bar/tile.
// ---------------------------------------------------------------------------
__global__ __launch_bounds__(256, 2) void k_gemm_mma(const float* __restrict__ W1) {
    extern __shared__ uint32_t su[];
    const int tid = threadIdx.x;
    const int mt0 = blockIdx.x * 128;
    const int kc  = blockIdx.y;
    const int kBeg = kc * 512;
    const int kEnd = (kc == kSPLIT - 1) ? kKDIM : kBeg + 512;

    const int warp = tid >> 5, lane = tid & 31;
    const int wr = warp & 3, wc = warp >> 2;
    const int wm = wr * 32, wn = wc * 32;
    const int gid = lane >> 2, tig = lane & 3;

    // fill mappings
    const int ar  = tid >> 1;          // A row 0..127
    const int ak0 = (tid & 1) * 16;    // A k base in tile
    const int bn  = tid >> 2;          // B n 0..63
    const int bk0 = (tid & 3) * 8;     // B k base in tile

    const float* asrc = g_bsum + (size_t)(mt0 + ar) * kKDIM;

    float d[2][4][4];
#pragma unroll
    for (int mt = 0; mt < 2; mt++)
#pragma unroll
        for (int n8 = 0; n8 < 4; n8++)
#pragma unroll
            for (int e = 0; e < 4; e++) d[mt][n8][e] = 0.f;

    float4 ra[4];   // A staging (16 fp32)
    float  rb[8];   // B staging (8 fp32)

    auto stage = [&](int t0) {
#pragma unroll
        for (int q = 0; q < 4; q++) {
            const int k = t0 + ak0 + q * 4;
            ra[q] = make_float4(0.f, 0.f, 0.f, 0.f);
            if (k < kEnd) ra[q] = *reinterpret_cast<const float4*>(asrc + k);
        }
#pragma unroll
        for (int j = 0; j < 8; j++) {
            const int k = t0 + bk0 + j;
            rb[j] = (k < kEnd) ? W1[(size_t)k * 64 + bn] : 0.f;
        }
    };

    auto commit = [&](int buf) {
        uint32_t* base = su + buf * kBufU;
#pragma unroll
        for (int q = 0; q < 4; q++) {
            uint32_t l01, l23;
            const uint32_t h01 = pack_hi(ra[q].x, ra[q].y, l01);
            const uint32_t h23 = pack_hi(ra[q].z, ra[q].w, l23);
            const int ci = ar * kRS + ak0 / 2 + q * 2;
            base[kAh + ci]     = h01;  base[kAh + ci + 1] = h23;
            base[kAl + ci]     = l01;  base[kAl + ci + 1] = l23;
        }
#pragma unroll
        for (int j = 0; j < 8; j += 2) {
            uint32_t l;
            const uint32_t h = pack_hi(rb[j], rb[j + 1], l);
            const int ci = bn * kRS + bk0 / 2 + j / 2;
            base[kBh + ci] = h;
            base[kBl + ci] = l;
        }
    };

    stage(kBeg);
    int buf = 0;
    for (int t0 = kBeg; t0 < kEnd; t0 += 32, buf ^= 1) {
        commit(buf);
        __syncthreads();
        if (t0 + 32 < kEnd) stage(t0 + 32);   // overlap next-tile LDG with MMA

        const uint32_t* sbuf = su + buf * kBufU;
#pragma unroll
        for (int kh = 0; kh < 2; kh++) {
            const int ci = tig + kh * 8;
            // B frags (hi+lo) for 4 n8-tiles
            uint32_t bh0[4], bh1[4], bl0[4], bl1[4];
#pragma unroll
            for (int n8 = 0; n8 < 4; n8++) {
                const int bro = (wn + n8 * 8 + gid) * kRS + ci;
                bh0[n8] = sbuf[kBh + bro];  bh1[n8] = sbuf[kBh + bro + 4];
                bl0[n8] = sbuf[kBl + bro];  bl1[n8] = sbuf[kBl + bro + 4];
            }
            // A frags (hi+lo) for 2 m16-tiles
            uint32_t ah[2][4], al[2][4];
#pragma unroll
            for (int mt = 0; mt < 2; mt++) {
                const int r0 = (wm + mt * 16 + gid) * kRS + ci;
                const int r8 = r0 + 8 * kRS;
                ah[mt][0] = sbuf[kAh + r0];  ah[mt][1] = sbuf[kAh + r8];
                ah[mt][2] = sbuf[kAh + r0 + 4];  ah[mt][3] = sbuf[kAh + r8 + 4];
                al[mt][0] = sbuf[kAl + r0];  al[mt][1] = sbuf[kAl + r8];
                al[mt][2] = sbuf[kAl + r0 + 4];  al[mt][3] = sbuf[kAl + r8 + 4];
            }
#pragma unroll
            for (int mt = 0; mt < 2; mt++)
#pragma unroll
                for (int n8 = 0; n8 < 4; n8++) {
                    float* dd = d[mt][n8];
                    mma16816(dd[0], dd[1], dd[2], dd[3],
                             ah[mt][0], ah[mt][1], ah[mt][2], ah[mt][3],
                             bh0[n8], bh1[n8]);
                    mma16816(dd[0], dd[1], dd[2], dd[3],
                             al[mt][0], al[mt][1], al[mt][2], al[mt][3],
                             bh0[n8], bh1[n8]);
                    mma16816(dd[0], dd[1], dd[2], dd[3],
                             ah[mt][0], ah[mt][1], ah[mt][2], ah[mt][3],
                             bl0[n8], bl1[n8]);
                }
        }
        // single barrier per tile: next commit writes the OTHER buffer.
    }

    // epilogue: D frag (m16n8): d0,d1 = (gid, 2*tig, +1); d2,d3 = (gid+8, ...)
    float* pb = g_part + (size_t)kc * kMR * 64;
#pragma unroll
    for (int mt = 0; mt < 2; mt++) {
        const int row0 = mt0 + wm + mt * 16 + gid;
#pragma unroll
        for (int n8 = 0; n8 < 4; n8++) {
            const int col = wn + n8 * 8 + tig * 2;
            *reinterpret_cast<float2*>(pb + (size_t)row0 * 64 + col) =
                make_float2(d[mt][n8][0], d[mt][n8][1]);
            *reinterpret_cast<float2*>(pb + (size_t)(row0 + 8) * 64 + col) =
                make_float2(d[mt][n8][2], d[mt][n8][3]);
        }
    }
}

// ---------------------------------------------------------------------------
// Kernel 3: sum split-K partials + adjacent half-block rows, scale, bias,
// exact gelu, dot W2 -> logits; window_mask. One warp per window.
// ---------------------------------------------------------------------------
__global__ __launch_bounds__(256) void k_fin(const float* __restrict__ b1,
                                             const float* __restrict__ W2,
                                             const float* __restrict__ b2,
                                             float* __restrict__ out) {
    const int w    = (blockIdx.x * 256 + threadIdx.x) >> 5;  // 0..4095
    const int lane = threadIdx.x & 31;
    const int b    = w >> 9;
    const int wi   = w & 511;
    const int r0   = b * kNBpB + wi;
    const bool two = (wi < 511);     // window 511's upper half-block is OOB

    const float cnt = g_cnt[r0] + (two ? g_cnt[r0 + 1] : 0.f);
    const float inv = 1.f / fmaxf(cnt, 1.f);
    if (lane == 0) out[kB * kNW + w] = (cnt > 0.f) ? 1.f : 0.f;  // window_mask

    float r = 0.f;
#pragma unroll
    for (int h = 0; h < 2; h++) {
        const int n = lane + h * 32;
        float s = 0.f;
#pragma unroll
        for (int c = 0; c < kSPLIT; c++) {
            const float* pc = g_part + ((size_t)c * kMR + r0) * 64 + n;
            s += pc[0];
            if (two) s += pc[64];
        }
        const float x = s * inv + b1[n];
        const float g = 0.5f * x * (1.f + erff(x * 0.70710678118654752f));
        r += g * W2[n];
    }
#pragma unroll
    for (int o = 16; o; o >>= 1) r += __shfl_xor_sync(0xffffffffu, r, o);
    if (lane == 0) out[w] = r + b2[0];   // window_logits
}

extern "C" void kernel_launch(void* const* d_in, const int* in_sizes, int n_in,
                              void* d_out, int out_size) {
    const float* hid  = (const float*)d_in[0];  // hidden_states (8,4096,2048)
    const int*   am   = (const int*)d_in[1];    // attention_mask (8,4096)
    const float* hint = (const float*)d_in[2];  // hint_features (8,4096,4)
    const float* W1   = (const float*)d_in[3];  // (2052,64)
    const float* b1   = (const float*)d_in[4];  // (64,)
    const float* W2   = (const float*)d_in[5];  // (64,1)
    const float* b2   = (const float*)d_in[6];  // (1,)
    float* out = (float*)d_out;                 // [logits (8*512) | mask (8*512)]

    cudaFuncSetAttribute(k_gemm_mma, cudaFuncAttributeMaxDynamicSharedMemorySize,
                         kSmemDyn);

    dim3 g1(kNBpB, kB);
    k_pool<<<g1, 256>>>(hid, am, hint);

    dim3 g2(kMR / 128, kSPLIT);                 // 32 x 4 = 128 CTAs
    k_gemm_mma<<<g2, 256, kSmemDyn>>>(W1);

    k_fin<<<kB * kNW * 32 / 256, 256>>>(b1, W2, b2, out);
}

// round 13
// speedup vs baseline: 2.5808x; 1.0600x over previous
#include <cuda_runtime.h>
#include <cuda_bf16.h>
#include <math.h>
#include <stdint.h>

// Problem constants
static constexpr int kB    = 8;
static constexpr int kS    = 4096;
static constexpr int kH    = 2048;
static constexpr int kHINT = 4;
static constexpr int kNBpB = 512;        // half-blocks per batch
static constexpr int kKDIM = 2052;       // H + HINT
static constexpr int kNW   = 512;        // windows per batch
static constexpr int kMR   = kB * kNBpB; // 4096 GEMM rows = 32 m-tiles of 128
static constexpr int kSPLIT = 8;
static constexpr int kCHUNK = 256;       // last chunk = 2052 - 7*256 = 260

// Scratch: only split-K partials now (pooling fused into the GEMM).
__device__ float g_part[(size_t)kSPLIT * kMR * 64];

// ---------------------------------------------------------------------------
// mma.sync m16n8k16 bf16 (sm_80+ base-target; HMMA on sm_103)
// ---------------------------------------------------------------------------
__device__ __forceinline__ void mma16816(float& d0, float& d1, float& d2, float& d3,
                                         uint32_t a0, uint32_t a1, uint32_t a2, uint32_t a3,
                                         uint32_t b0, uint32_t b1) {
    asm volatile(
        "mma.sync.aligned.m16n8k16.row.col.f32.bf16.bf16.f32 "
        "{%0,%1,%2,%3}, {%4,%5,%6,%7}, {%8,%9}, {%0,%1,%2,%3};"
        : "+f"(d0), "+f"(d1), "+f"(d2), "+f"(d3)
        : "r"(a0), "r"(a1), "r"(a2), "r"(a3), "r"(b0), "r"(b1));
}

__device__ __forceinline__ uint32_t pack_hi(float x, float y, uint32_t& lo) {
    __nv_bfloat162 h = __float22bfloat162_rn(make_float2(x, y));
    float rx = x - __bfloat162float(__low2bfloat16(h));
    float ry = y - __bfloat162float(__high2bfloat16(h));
    __nv_bfloat162 l = __float22bfloat162_rn(make_float2(rx, ry));
    lo = *reinterpret_cast<uint32_t*>(&l);
    return *reinterpret_cast<uint32_t*>(&h);
}

// smem layout (u32 units), row stride 20 u32 (80B) -> conflict-free frag loads
static constexpr int kRS   = 20;
static constexpr int kAh   = 0;            // 128 rows
static constexpr int kAl   = 128 * kRS;    // 2560
static constexpr int kBh   = 256 * kRS;    // 5120
static constexpr int kBl   = 320 * kRS;    // 6400
static constexpr int kBufU = 384 * kRS;    // 7680 u32 per buffer
static constexpr int kSmemDyn = (2 * kBufU + 1024) * 4;   // + mask floats = 65536 B

// ---------------------------------------------------------------------------
// Fused kernel: masked window pooling + split-precision bf16 tensor GEMM.
//   g_part[kc][r][n] = sum_{k in chunk} (sum_j mask_j * feat[tok_j][k]) * W1[k][n]
// CTA: 128 half-block rows (1024 tokens, one batch) x 64 n x one K chunk.
// Per k-tile of 32: stage = pool 8 masked token rows per half-block from HBM
// (mask-skip), convert fp32 -> bf16 hi/lo, MMA 3 terms. Double-buffered.
// ---------------------------------------------------------------------------
__global__ __launch_bounds__(256, 2) void k_fuse(const float* __restrict__ hid,
                                                 const int* __restrict__ am,
                                                 const float* __restrict__ hint,
                                                 const float* __restrict__ W1) {
    extern __shared__ uint32_t su[];
    float* smf = reinterpret_cast<float*>(su + 2 * kBufU);   // 1024 token masks

    const int tid = threadIdx.x;
    const int r0g = blockIdx.x * 128;           // global half-block row base
    const int kc  = blockIdx.y;
    const int kBeg = kc * kCHUNK;
    const int kEnd = (kc == kSPLIT - 1) ? kKDIM : kBeg + kCHUNK;

    const int bat     = r0g >> 9;
    const int tokBase = bat * kS + (r0g & 511) * 8;   // 1024 contiguous tokens

    // token masks -> smem floats
#pragma unroll
    for (int i = 0; i < 4; i++)
        smf[tid + i * 256] = (float)am[tokBase + tid + i * 256];

    const int warp = tid >> 5, lane = tid & 31;
    const int wr = warp & 3, wc = warp >> 2;
    const int wm = wr * 32, wn = wc * 32;
    const int gid = lane >> 2, tig = lane & 3;

    // fill mappings
    const int ahb = tid >> 1;          // A half-block 0..127
    const int ak0 = (tid & 1) * 16;    // A k base in tile
    const int bn  = tid >> 2;          // B n 0..63
    const int bk0 = (tid & 3) * 8;     // B k base in tile

    const float* arow0 = hid + (size_t)(tokBase + ahb * 8) * kH;   // token row 0 of hb
    const float* hrow0 = hint + (size_t)(tokBase + ahb * 8) * kHINT;

    float d[2][4][4];
#pragma unroll
    for (int mt = 0; mt < 2; mt++)
#pragma unroll
        for (int n8 = 0; n8 < 4; n8++)
#pragma unroll
            for (int e = 0; e < 4; e++) d[mt][n8][e] = 0.f;

    float4 acc[4];   // pooled A staging (16 k values)
    float  rb[8];    // B staging

    __syncthreads();   // masks visible

    auto stage = [&](int t0) {
#pragma unroll
        for (int q = 0; q < 4; q++) acc[q] = make_float4(0.f, 0.f, 0.f, 0.f);
        const int kq0 = t0 + ak0;
        if (kq0 + 16 <= kH) {          // fast path: pure hidden, vectorized
#pragma unroll
            for (int j = 0; j < 8; j++) {
                const float w = smf[ahb * 8 + j];
                if (w != 0.f) {
                    const float4* rp = reinterpret_cast<const float4*>(
                        arow0 + (size_t)j * kH + kq0);
#pragma unroll
                    for (int q = 0; q < 4; q++) {
                        const float4 v = rp[q];
                        acc[q].x += w * v.x; acc[q].y += w * v.y;
                        acc[q].z += w * v.z; acc[q].w += w * v.w;
                    }
                }
            }
        } else {                        // tail: hidden/hint/zero per element
#pragma unroll
            for (int j = 0; j < 8; j++) {
                const float w = smf[ahb * 8 + j];
                if (w != 0.f) {
                    const float* rp = arow0 + (size_t)j * kH;
                    const float* hp = hrow0 + (size_t)j * kHINT;
                    float* a = &acc[0].x;
#pragma unroll
                    for (int e = 0; e < 16; e++) {
                        const int k = kq0 + e;
                        float v = 0.f;
                        if (k < kH) v = rp[k];
                        else if (k < kKDIM) v = hp[k - kH];
                        a[e] += w * v;
                    }
                }
            }
        }
#pragma unroll
        for (int j = 0; j < 8; j++) {
            const int k = t0 + bk0 + j;
            rb[j] = (k < kKDIM) ? W1[(size_t)k * 64 + bn] : 0.f;
        }
    };

    auto commit = [&](int buf) {
        uint32_t* base = su + buf * kBufU;
#pragma unroll
        for (int q = 0; q < 4; q++) {
            uint32_t l01, l23;
            const uint32_t h01 = pack_hi(acc[q].x, acc[q].y, l01);
            const uint32_t h23 = pack_hi(acc[q].z, acc[q].w, l23);
            const int ci = ahb * kRS + ak0 / 2 + q * 2;
            base[kAh + ci] = h01;  base[kAh + ci + 1] = h23;
            base[kAl + ci] = l01;  base[kAl + ci + 1] = l23;
        }
#pragma unroll
        for (int j = 0; j < 8; j += 2) {
            uint32_t l;
            const uint32_t h = pack_hi(rb[j], rb[j + 1], l);
            const int ci = bn * kRS + bk0 / 2 + j / 2;
            base[kBh + ci] = h;
            base[kBl + ci] = l;
        }
    };

    stage(kBeg);
    int buf = 0;
    for (int t0 = kBeg; t0 < kEnd; t0 += 32, buf ^= 1) {
        commit(buf);
        __syncthreads();
        if (t0 + 32 < kEnd) stage(t0 + 32);   // pooling of next tile overlaps MMA

        const uint32_t* sbuf = su + buf * kBufU;
#pragma unroll
        for (int kh = 0; kh < 2; kh++) {
            const int ci = tig + kh * 8;
            uint32_t bh0[4], bh1[4], bl0[4], bl1[4];
#pragma unroll
            for (int n8 = 0; n8 < 4; n8++) {
                const int bro = (wn + n8 * 8 + gid) * kRS + ci;
                bh0[n8] = sbuf[kBh + bro];  bh1[n8] = sbuf[kBh + bro + 4];
                bl0[n8] = sbuf[kBl + bro];  bl1[n8] = sbuf[kBl + bro + 4];
            }
            uint32_t ah[2][4], al[2][4];
#pragma unroll
            for (int mt = 0; mt < 2; mt++) {
                const int r0 = (wm + mt * 16 + gid) * kRS + ci;
                const int r8 = r0 + 8 * kRS;
                ah[mt][0] = sbuf[kAh + r0];      ah[mt][1] = sbuf[kAh + r8];
                ah[mt][2] = sbuf[kAh + r0 + 4];  ah[mt][3] = sbuf[kAh + r8 + 4];
                al[mt][0] = sbuf[kAl + r0];      al[mt][1] = sbuf[kAl + r8];
                al[mt][2] = sbuf[kAl + r0 + 4];  al[mt][3] = sbuf[kAl + r8 + 4];
            }
#pragma unroll
            for (int mt = 0; mt < 2; mt++)
#pragma unroll
                for (int n8 = 0; n8 < 4; n8++) {
                    float* dd = d[mt][n8];
                    mma16816(dd[0], dd[1], dd[2], dd[3],
                             ah[mt][0], ah[mt][1], ah[mt][2], ah[mt][3],
                             bh0[n8], bh1[n8]);
                    mma16816(dd[0], dd[1], dd[2], dd[3],
                             al[mt][0], al[mt][1], al[mt][2], al[mt][3],
                             bh0[n8], bh1[n8]);
                    mma16816(dd[0], dd[1], dd[2], dd[3],
                             ah[mt][0], ah[mt][1], ah[mt][2], ah[mt][3],
                             bl0[n8], bl1[n8]);
                }
        }
        // single barrier per tile: next commit writes the OTHER buffer.
    }

    // epilogue: write partials
    float* pb = g_part + (size_t)kc * kMR * 64;
#pragma unroll
    for (int mt = 0; mt < 2; mt++) {
        const int row0 = r0g + wm + mt * 16 + gid;
#pragma unroll
        for (int n8 = 0; n8 < 4; n8++) {
            const int col = wn + n8 * 8 + tig * 2;
            *reinterpret_cast<float2*>(pb + (size_t)row0 * 64 + col) =
                make_float2(d[mt][n8][0], d[mt][n8][1]);
            *reinterpret_cast<float2*>(pb + (size_t)(row0 + 8) * 64 + col) =
                make_float2(d[mt][n8][2], d[mt][n8][3]);
        }
    }
}

// ---------------------------------------------------------------------------
// Kernel 2: sum split-K partials + adjacent half-block rows, count from the
// raw mask, scale, bias, exact gelu, dot W2 -> logits; window_mask.
// One warp per window.
// ---------------------------------------------------------------------------
__global__ __launch_bounds__(256) void k_fin(const int* __restrict__ am,
                                             const float* __restrict__ b1,
                                             const float* __restrict__ W2,
                                             const float* __restrict__ b2,
                                             float* __restrict__ out) {
    const int w    = (blockIdx.x * 256 + threadIdx.x) >> 5;  // 0..4095
    const int lane = threadIdx.x & 31;
    const int b    = w >> 9;
    const int wi   = w & 511;
    const int r0   = b * kNBpB + wi;
    const bool two = (wi < 511);     // window 511's upper half-block is OOB

    // window count from raw mask (16 positions, pos >= S masked off)
    float mv = 0.f;
    if (lane < 16) {
        const int p = wi * 8 + lane;
        if (p < kS) mv = (float)am[b * kS + p];
    }
#pragma unroll
    for (int o = 8; o; o >>= 1) mv += __shfl_xor_sync(0xffffffffu, mv, o);
    const float cnt = __shfl_sync(0xffffffffu, mv, 0);
    const float inv = 1.f / fmaxf(cnt, 1.f);
    if (lane == 0) out[kB * kNW + w] = (cnt > 0.f) ? 1.f : 0.f;  // window_mask

    float r = 0.f;
#pragma unroll
    for (int h = 0; h < 2; h++) {
        const int n = lane + h * 32;
        float s = 0.f;
#pragma unroll
        for (int c = 0; c < kSPLIT; c++) {
            const float* pc = g_part + ((size_t)c * kMR + r0) * 64 + n;
            s += pc[0];
            if (two) s += pc[64];
        }
        const float x = s * inv + b1[n];
        const float g = 0.5f * x * (1.f + erff(x * 0.70710678118654752f));
        r += g * W2[n];
    }
#pragma unroll
    for (int o = 16; o; o >>= 1) r += __shfl_xor_sync(0xffffffffu, r, o);
    if (lane == 0) out[w] = r + b2[0];   // window_logits
}

extern "C" void kernel_launch(void* const* d_in, const int* in_sizes, int n_in,
                              void* d_out, int out_size) {
    const float* hid  = (const float*)d_in[0];  // hidden_states (8,4096,2048)
    const int*   am   = (const int*)d_in[1];    // attention_mask (8,4096)
    const float* hint = (const float*)d_in[2];  // hint_features (8,4096,4)
    const float* W1   = (const float*)d_in[3];  // (2052,64)
    const float* b1   = (const float*)d_in[4];  // (64,)
    const float* W2   = (const float*)d_in[5];  // (64,1)
    const float* b2   = (const float*)d_in[6];  // (1,)
    float* out = (float*)d_out;                 // [logits (8*512) | mask (8*512)]

    cudaFuncSetAttribute(k_fuse, cudaFuncAttributeMaxDynamicSharedMemorySize,
                         kSmemDyn);

    dim3 g(kMR / 128, kSPLIT);                  // 32 x 8 = 256 CTAs
    k_fuse<<<g, 256, kSmemDyn>>>(hid, am, hint, W1);

    k_fin<<<kB * kNW * 32 / 256, 256>>>(am, b1, W2, b2, out);
}

// round 14
// speedup vs baseline: 2.6136x; 1.0127x over previous
#include <cuda_runtime.h>
#include <cuda_bf16.h>
#include <math.h>
#include <stdint.h>

// Problem constants
static constexpr int kB    = 8;
static constexpr int kS    = 4096;
static constexpr int kH    = 2048;
static constexpr int kHINT = 4;
static constexpr int kNBpB = 512;        // half-blocks per batch
static constexpr int kKDIM = 2052;       // H + HINT
static constexpr int kNW   = 512;        // windows per batch
static constexpr int kMR   = kB * kNBpB; // 4096 GEMM rows = 32 m-tiles of 128
static constexpr int kSPLIT = 8;
static constexpr int kCHUNK = 256;       // last chunk = 2052 - 7*256 = 260

// Scratch: split-K partials
__device__ float g_part[(size_t)kSPLIT * kMR * 64];

// ---------------------------------------------------------------------------
// mma.sync m16n8k16 bf16 (sm_80+ base-target; HMMA on sm_103)
// ---------------------------------------------------------------------------
__device__ __forceinline__ void mma16816(float& d0, float& d1, float& d2, float& d3,
                                         uint32_t a0, uint32_t a1, uint32_t a2, uint32_t a3,
                                         uint32_t b0, uint32_t b1) {
    asm volatile(
        "mma.sync.aligned.m16n8k16.row.col.f32.bf16.bf16.f32 "
        "{%0,%1,%2,%3}, {%4,%5,%6,%7}, {%8,%9}, {%0,%1,%2,%3};"
        : "+f"(d0), "+f"(d1), "+f"(d2), "+f"(d3)
        : "r"(a0), "r"(a1), "r"(a2), "r"(a3), "r"(b0), "r"(b1));
}

// Predicated 16B global load: no branch (no BSSY/BSYNC), request suppressed
// when w == 0 (DRAM traffic saved), result forced to zero.
__device__ __forceinline__ float4 ldg_pred(const float* p, float w) {
    float4 v = make_float4(0.f, 0.f, 0.f, 0.f);
    asm volatile(
        "{\n\t"
        ".reg .pred p;\n\t"
        "setp.ne.f32 p, %5, 0f00000000;\n\t"
        "@p ld.global.nc.v4.f32 {%0,%1,%2,%3}, [%4];\n\t"
        "}"
        : "+f"(v.x), "+f"(v.y), "+f"(v.z), "+f"(v.w)
        : "l"(p), "f"(w));
    return v;
}

__device__ __forceinline__ uint32_t pack_hi(float x, float y, uint32_t& lo) {
    __nv_bfloat162 h = __float22bfloat162_rn(make_float2(x, y));
    float rx = x - __bfloat162float(__low2bfloat16(h));
    float ry = y - __bfloat162float(__high2bfloat16(h));
    __nv_bfloat162 l = __float22bfloat162_rn(make_float2(rx, ry));
    lo = *reinterpret_cast<uint32_t*>(&l);
    return *reinterpret_cast<uint32_t*>(&h);
}

// smem layout (u32 units), row stride 20 u32 (80B) -> conflict-free frag loads
static constexpr int kRS   = 20;
static constexpr int kAh   = 0;            // 128 rows
static constexpr int kAl   = 128 * kRS;    // 2560
static constexpr int kBh   = 256 * kRS;    // 5120
static constexpr int kBl   = 320 * kRS;    // 6400
static constexpr int kBufU = 384 * kRS;    // 7680 u32 per buffer
static constexpr int kSmemDyn = (2 * kBufU + 1024) * 4;   // + mask floats = 65536 B

// ---------------------------------------------------------------------------
// Fused kernel: masked window pooling + split-precision bf16 tensor GEMM.
//   g_part[kc][r][n] = sum_{k in chunk} (sum_j mask_j * feat[tok_j][k]) * W1[k][n]
// CTA: 128 half-block rows (1024 tokens, one batch) x 64 n x one K chunk.
// Stage = pool 8 masked token rows per half-block (predicated LDG.128, no
// branches), convert fp32 -> bf16 hi/lo, MMA 3 terms. Double-buffered.
// ---------------------------------------------------------------------------
__global__ __launch_bounds__(256, 2) void k_fuse(const float* __restrict__ hid,
                                                 const int* __restrict__ am,
                                                 const float* __restrict__ hint,
                                                 const float* __restrict__ W1) {
    extern __shared__ uint32_t su[];
    float* smf = reinterpret_cast<float*>(su + 2 * kBufU);   // 1024 token masks

    const int tid = threadIdx.x;
    const int r0g = blockIdx.x * 128;           // global half-block row base
    const int kc  = blockIdx.y;
    const int kBeg = kc * kCHUNK;
    const int kEnd = (kc == kSPLIT - 1) ? kKDIM : kBeg + kCHUNK;

    const int bat     = r0g >> 9;
    const int tokBase = bat * kS + (r0g & 511) * 8;   // 1024 contiguous tokens

    // token masks -> smem floats
#pragma unroll
    for (int i = 0; i < 4; i++)
        smf[tid + i * 256] = (float)am[tokBase + tid + i * 256];

    const int warp = tid >> 5, lane = tid & 31;
    const int wr = warp & 3, wc = warp >> 2;
    const int wm = wr * 32, wn = wc * 32;
    const int gid = lane >> 2, tig = lane & 3;

    // fill mappings
    const int ahb = tid >> 1;          // A half-block 0..127
    const int ak0 = (tid & 1) * 16;    // A k base in tile
    const int bn  = tid >> 2;          // B n 0..63
    const int bk0 = (tid & 3) * 8;     // B k base in tile

    const float* arow0 = hid + (size_t)(tokBase + ahb * 8) * kH;
    const float* hrow0 = hint + (size_t)(tokBase + ahb * 8) * kHINT;

    float d[2][4][4];
#pragma unroll
    for (int mt = 0; mt < 2; mt++)
#pragma unroll
        for (int n8 = 0; n8 < 4; n8++)
#pragma unroll
            for (int e = 0; e < 4; e++) d[mt][n8][e] = 0.f;

    float4 acc[4];   // pooled A staging (16 k values)
    float  rb[8];    // B staging

    __syncthreads();   // masks visible

    // hoist this thread's 8 row masks to registers (tile-invariant)
    float rm[8];
#pragma unroll
    for (int j = 0; j < 8; j++) rm[j] = smf[ahb * 8 + j];

    auto stage = [&](int t0) {
#pragma unroll
        for (int q = 0; q < 4; q++) acc[q] = make_float4(0.f, 0.f, 0.f, 0.f);
        const int kq0 = t0 + ak0;
        if (kq0 + 16 <= kH) {          // fast path: pure hidden, predicated v4 loads
#pragma unroll
            for (int j = 0; j < 8; j++) {
                const float w = rm[j];
                const float* rp = arow0 + (size_t)j * kH + kq0;
                const float4 v0 = ldg_pred(rp,      w);
                const float4 v1 = ldg_pred(rp + 4,  w);
                const float4 v2 = ldg_pred(rp + 8,  w);
                const float4 v3 = ldg_pred(rp + 12, w);
                acc[0].x += w * v0.x; acc[0].y += w * v0.y;
                acc[0].z += w * v0.z; acc[0].w += w * v0.w;
                acc[1].x += w * v1.x; acc[1].y += w * v1.y;
                acc[1].z += w * v1.z; acc[1].w += w * v1.w;
                acc[2].x += w * v2.x; acc[2].y += w * v2.y;
                acc[2].z += w * v2.z; acc[2].w += w * v2.w;
                acc[3].x += w * v3.x; acc[3].y += w * v3.y;
                acc[3].z += w * v3.z; acc[3].w += w * v3.w;
            }
        } else {                        // tail: hidden/hint/zero per element
#pragma unroll
            for (int j = 0; j < 8; j++) {
                const float w = rm[j];
                if (w != 0.f) {
                    const float* rp = arow0 + (size_t)j * kH;
                    const float* hp = hrow0 + (size_t)j * kHINT;
                    float* a = &acc[0].x;
#pragma unroll
                    for (int e = 0; e < 16; e++) {
                        const int k = kq0 + e;
                        float v = 0.f;
                        if (k < kH) v = rp[k];
                        else if (k < kKDIM) v = hp[k - kH];
                        a[e] += w * v;
                    }
                }
            }
        }
#pragma unroll
        for (int j = 0; j < 8; j++) {
            const int k = t0 + bk0 + j;
            rb[j] = (k < kKDIM) ? W1[(size_t)k * 64 + bn] : 0.f;
        }
    };

    auto commit = [&](int buf) {
        uint32_t* base = su + buf * kBufU;
#pragma unroll
        for (int q = 0; q < 4; q++) {
            uint32_t l01, l23;
            const uint32_t h01 = pack_hi(acc[q].x, acc[q].y, l01);
            const uint32_t h23 = pack_hi(acc[q].z, acc[q].w, l23);
            const int ci = ahb * kRS + ak0 / 2 + q * 2;
            base[kAh + ci] = h01;  base[kAh + ci + 1] = h23;
            base[kAl + ci] = l01;  base[kAl + ci + 1] = l23;
        }
#pragma unroll
        for (int j = 0; j < 8; j += 2) {
            uint32_t l;
            const uint32_t h = pack_hi(rb[j], rb[j + 1], l);
            const int ci = bn * kRS + bk0 / 2 + j / 2;
            base[kBh + ci] = h;
            base[kBl + ci] = l;
        }
    };

    stage(kBeg);
    int buf = 0;
    for (int t0 = kBeg; t0 < kEnd; t0 += 32, buf ^= 1) {
        commit(buf);
        __syncthreads();
        if (t0 + 32 < kEnd) stage(t0 + 32);   // pooling of next tile overlaps MMA

        const uint32_t* sbuf = su + buf * kBufU;
#pragma unroll
        for (int kh = 0; kh < 2; kh++) {
            const int ci = tig + kh * 8;
            uint32_t bh0[4], bh1[4], bl0[4], bl1[4];
#pragma unroll
            for (int n8 = 0; n8 < 4; n8++) {
                const int bro = (wn + n8 * 8 + gid) * kRS + ci;
                bh0[n8] = sbuf[kBh + bro];  bh1[n8] = sbuf[kBh + bro + 4];
                bl0[n8] = sbuf[kBl + bro];  bl1[n8] = sbuf[kBl + bro + 4];
            }
            uint32_t ah[2][4], al[2][4];
#pragma unroll
            for (int mt = 0; mt < 2; mt++) {
                const int r0 = (wm + mt * 16 + gid) * kRS + ci;
                const int r8 = r0 + 8 * kRS;
                ah[mt][0] = sbuf[kAh + r0];      ah[mt][1] = sbuf[kAh + r8];
                ah[mt][2] = sbuf[kAh + r0 + 4];  ah[mt][3] = sbuf[kAh + r8 + 4];
                al[mt][0] = sbuf[kAl + r0];      al[mt][1] = sbuf[kAl + r8];
                al[mt][2] = sbuf[kAl + r0 + 4];  al[mt][3] = sbuf[kAl + r8 + 4];
            }
#pragma unroll
            for (int mt = 0; mt < 2; mt++)
#pragma unroll
                for (int n8 = 0; n8 < 4; n8++) {
                    float* dd = d[mt][n8];
                    mma16816(dd[0], dd[1], dd[2], dd[3],
                             ah[mt][0], ah[mt][1], ah[mt][2], ah[mt][3],
                             bh0[n8], bh1[n8]);
                    mma16816(dd[0], dd[1], dd[2], dd[3],
                             al[mt][0], al[mt][1], al[mt][2], al[mt][3],
                             bh0[n8], bh1[n8]);
                    mma16816(dd[0], dd[1], dd[2], dd[3],
                             ah[mt][0], ah[mt][1], ah[mt][2], ah[mt][3],
                             bl0[n8], bl1[n8]);
                }
        }
        // single barrier per tile: next commit writes the OTHER buffer.
    }

    // epilogue: write partials
    float* pb = g_part + (size_t)kc * kMR * 64;
#pragma unroll
    for (int mt = 0; mt < 2; mt++) {
        const int row0 = r0g + wm + mt * 16 + gid;
#pragma unroll
        for (int n8 = 0; n8 < 4; n8++) {
            const int col = wn + n8 * 8 + tig * 2;
            *reinterpret_cast<float2*>(pb + (size_t)row0 * 64 + col) =
                make_float2(d[mt][n8][0], d[mt][n8][1]);
            *reinterpret_cast<float2*>(pb + (size_t)(row0 + 8) * 64 + col) =
                make_float2(d[mt][n8][2], d[mt][n8][3]);
        }
    }
}

// ---------------------------------------------------------------------------
// Kernel 2: sum split-K partials + adjacent half-block rows, count from raw
// mask, scale, bias, exact gelu, dot W2 -> logits; window_mask.
// One warp per window; lane owns cols {2*lane, 2*lane+1} (float2 loads).
// ---------------------------------------------------------------------------
__global__ __launch_bounds__(256) void k_fin(const int* __restrict__ am,
                                             const float* __restrict__ b1,
                                             const float* __restrict__ W2,
                                             const float* __restrict__ b2,
                                             float* __restrict__ out) {
    const int w    = (blockIdx.x * 256 + threadIdx.x) >> 5;  // 0..4095
    const int lane = threadIdx.x & 31;
    const int b    = w >> 9;
    const int wi   = w & 511;
    const int r0   = b * kNBpB + wi;
    const bool two = (wi < 511);     // window 511's upper half-block is OOB

    // window count from raw mask (16 positions, pos >= S masked off)
    float mv = 0.f;
    if (lane < 16) {
        const int p = wi * 8 + lane;
        if (p < kS) mv = (float)am[b * kS + p];
    }
#pragma unroll
    for (int o = 8; o; o >>= 1) mv += __shfl_xor_sync(0xffffffffu, mv, o);
    const float cnt = __shfl_sync(0xffffffffu, mv, 0);
    const float inv = 1.f / fmaxf(cnt, 1.f);
    if (lane == 0) out[kB * kNW + w] = (cnt > 0.f) ? 1.f : 0.f;  // window_mask

    const int c2 = lane * 2;
    float2 s = make_float2(0.f, 0.f);
#pragma unroll
    for (int c = 0; c < kSPLIT; c++) {
        const float* pc = g_part + ((size_t)c * kMR + r0) * 64 + c2;
        const float2 a = *reinterpret_cast<const float2*>(pc);
        s.x += a.x; s.y += a.y;
        if (two) {
            const float2 bb = *reinterpret_cast<const float2*>(pc + 64);
            s.x += bb.x; s.y += bb.y;
        }
    }
    const float x0 = s.x * inv + b1[c2];
    const float x1 = s.y * inv + b1[c2 + 1];
    const float g0 = 0.5f * x0 * (1.f + erff(x0 * 0.70710678118654752f));
    const float g1 = 0.5f * x1 * (1.f + erff(x1 * 0.70710678118654752f));
    float r = g0 * W2[c2] + g1 * W2[c2 + 1];
#pragma unroll
    for (int o = 16; o; o >>= 1) r += __shfl_xor_sync(0xffffffffu, r, o);
    if (lane == 0) out[w] = r + b2[0];   // window_logits
}

extern "C" void kernel_launch(void* const* d_in, const int* in_sizes, int n_in,
                              void* d_out, int out_size) {
    const float* hid  = (const float*)d_in[0];  // hidden_states (8,4096,2048)
    const int*   am   = (const int*)d_in[1];    // attention_mask (8,4096)
    const float* hint = (const float*)d_in[2];  // hint_features (8,4096,4)
    const float* W1   = (const float*)d_in[3];  // (2052,64)
    const float* b1   = (const float*)d_in[4];  // (64,)
    const float* W2   = (const float*)d_in[5];  // (64,1)
    const float* b2   = (const float*)d_in[6];  // (1,)
    float* out = (float*)d_out;                 // [logits (8*512) | mask (8*512)]

    cudaFuncSetAttribute(k_fuse, cudaFuncAttributeMaxDynamicSharedMemorySize,
                         kSmemDyn);

    dim3 g(kMR / 128, kSPLIT);                  // 32 x 8 = 256 CTAs
    k_fuse<<<g, 256, kSmemDyn>>>(hid, am, hint, W1);

    k_fin<<<kB * kNW * 32 / 256, 256>>>(am, b1, W2, b2, out);
}